// round 7
// baseline (speedup 1.0000x reference)
#include <cuda_runtime.h>
#include <cuda_bf16.h>

// Fixed problem shape
#define B_    4
#define N_    64
#define HW_   512
#define T_    64     // tile 64x64
#define MAXC  16     // labels per chunk

// Latency-optimized sparse fused kernel:
//  - warp 0: label compaction via direct LDG + ballot (no block syncs)
//  - warp 0 computes normalizations WHILE warps 1-7 build gaussians
//  - analytic normalization sigma*sqrt(2pi) for unclipped labels
//  - 2 __syncthreads on the common path
__global__ __launch_bounds__(256) void density_sparse3(
    const float* __restrict__ labels,   // (B, N, 2)
    const float* __restrict__ sigma_p,  // scalar
    float* __restrict__ out)            // (B, 1, 512, 512)
{
    __shared__ __align__(16) float s_gy[MAXC][T_];   // raw gy (4 KB)
    __shared__ __align__(16) float s_gx[MAXC][T_];   // raw gx (4 KB)
    __shared__ __align__(16) float s_lab[N_ * 2];
    __shared__ float s_inv[MAXC];                    // 1/(sum_x*sum_y)
    __shared__ int   s_list[N_];
    __shared__ int   s_cnt;

    const int b  = blockIdx.z;
    const int h0 = blockIdx.y * T_;
    const int w0 = blockIdx.x * T_;
    const int t  = threadIdx.x;                 // 0..255
    const int lane = t & 31;

    const float sigma  = sigma_p[0];
    const float inv2   = 1.0f / (2.0f * sigma * sigma);
    const float R      = 6.5f * sigma;          // e^{-21} truncation
    const float s_an   = sigma * 2.5066282746310002f;   // sigma*sqrt(2*pi)

    // all threads: stage labels to smem (needed by exp + norm phases)
    if (t < N_ * 2) s_lab[t] = __ldg(&labels[b * N_ * 2 + t]);

    // warp 0: compaction. Each lane tests labels lane and lane+32.
    if (t < 32) {
        const float2* lab2 = (const float2*)labels + b * N_;
        float2 p0 = __ldg(&lab2[lane]);
        float2 p1 = __ldg(&lab2[lane + 32]);
        const float wlo = (float)w0 - R, whi = (float)(w0 + T_ - 1) + R;
        const float hlo = (float)h0 - R, hhi = (float)(h0 + T_ - 1) + R;
        bool a0 = (p0.x >= wlo) && (p0.x <= whi) && (p0.y >= hlo) && (p0.y <= hhi);
        bool a1 = (p1.x >= wlo) && (p1.x <= whi) && (p1.y >= hlo) && (p1.y <= hhi);
        unsigned m0 = __ballot_sync(0xFFFFFFFFu, a0);
        unsigned m1 = __ballot_sync(0xFFFFFFFFu, a1);
        unsigned below = (1u << lane) - 1u;
        if (a0) s_list[__popc(m0 & below)] = lane;
        if (a1) s_list[__popc(m0) + __popc(m1 & below)] = lane + 32;
        if (lane == 0) s_cnt = __popc(m0) + __popc(m1);
    }
    __syncthreads();                               // BAR #1
    const int cnt = s_cnt;

    float acc[4][4];
    #pragma unroll
    for (int i = 0; i < 4; i++)
        #pragma unroll
        for (int j = 0; j < 4; j++) acc[i][j] = 0.0f;

    const int tx = t & 15;      // 4 cols each
    const int ty = t >> 4;      // 4 rows each (0..15)

    for (int c0 = 0; c0 < cnt; c0 += MAXC) {
        const int nc = min(MAXC, cnt - c0);

        if (t < 32) {
            // ---- warp 0: normalization, lane-per-(label,axis) --------------
            const int li   = lane >> 1;            // 0..15
            const int axis = lane & 1;             // 0 = x, 1 = y
            float s = s_an;
            float l = 0.0f;
            if (li < nc) l = s_lab[2 * s_list[c0 + li] + axis];
            if (li < nc && (l < R || l > 511.0f - R)) {
                // border-clipped: explicit serial sum over the window
                int lo = (int)ceilf(l - R);  if (lo < 0) lo = 0;
                int hi = (int)floorf(l + R); if (hi > HW_ - 1) hi = HW_ - 1;
                s = 0.0f;
                for (int i = lo; i <= hi; i++) {
                    float d = (float)i - l;
                    s += __expf(-d * d * inv2);
                }
            }
            float so = __shfl_xor_sync(0xFFFFFFFFu, s, 1);
            if (li < nc && axis == 0) s_inv[li] = 1.0f / (s * so);
        } else {
            // ---- warps 1-7: raw windowed gaussians (unscaled) --------------
            for (int idx = t - 32; idx < nc * (2 * T_); idx += 224) {
                const int li = idx >> 7;
                const int r  = idx & 127;
                const int n  = s_list[c0 + li];
                if (r < T_) {
                    float l = s_lab[2 * n + 1];
                    float d = (float)(h0 + r) - l;
                    s_gy[li][r] = (fabsf(d) <= R) ? __expf(-d * d * inv2) : 0.0f;
                } else {
                    float l = s_lab[2 * n];
                    float d = (float)(w0 + (r - T_)) - l;
                    s_gx[li][r - T_] = (fabsf(d) <= R) ? __expf(-d * d * inv2) : 0.0f;
                }
            }
        }
        __syncthreads();                           // BAR #2

        // ---- rank-nc outer-product accumulation (inv folded into a) --------
        #pragma unroll 4
        for (int li = 0; li < nc; li++) {
            const float inv = s_inv[li];
            float4 a  = *reinterpret_cast<const float4*>(&s_gy[li][ty * 4]);
            float4 bx = *reinterpret_cast<const float4*>(&s_gx[li][tx * 4]);
            a.x *= inv; a.y *= inv; a.z *= inv; a.w *= inv;
            acc[0][0] += a.x * bx.x; acc[0][1] += a.x * bx.y; acc[0][2] += a.x * bx.z; acc[0][3] += a.x * bx.w;
            acc[1][0] += a.y * bx.x; acc[1][1] += a.y * bx.y; acc[1][2] += a.y * bx.z; acc[1][3] += a.y * bx.w;
            acc[2][0] += a.z * bx.x; acc[2][1] += a.z * bx.y; acc[2][2] += a.z * bx.z; acc[2][3] += a.z * bx.w;
            acc[3][0] += a.w * bx.x; acc[3][1] += a.w * bx.y; acc[3][2] += a.w * bx.z; acc[3][3] += a.w * bx.w;
        }
        if (c0 + MAXC < cnt) __syncthreads();      // only if another chunk
    }

    // ---- store (zeros where no label overlaps) ------------------------------
    float* ob = out + ((size_t)b * HW_ + h0 + ty * 4) * HW_ + w0 + tx * 4;
    #pragma unroll
    for (int i = 0; i < 4; i++) {
        float4 r = make_float4(acc[i][0], acc[i][1], acc[i][2], acc[i][3]);
        *reinterpret_cast<float4*>(&ob[i * (size_t)HW_]) = r;
    }
}

extern "C" void kernel_launch(void* const* d_in, const int* in_sizes, int n_in,
                              void* d_out, int out_size) {
    // d_in[0]: batch_images (unused, shape only)
    // d_in[1]: batch_labels (4,64,2) f32
    // d_in[2]: sigma scalar f32
    const float* labels = (const float*)d_in[1];
    const float* sigma  = (const float*)d_in[2];
    float* out = (float*)d_out;

    dim3 grid(HW_ / T_, HW_ / T_, B_);   // (8, 8, 4) = 256 blocks
    density_sparse3<<<grid, 256>>>(labels, sigma, out);
}